// round 17
// baseline (speedup 1.0000x reference)
#include <cuda_runtime.h>
#include <cuda_bf16.h>
#include <cstdint>
#include <cstddef>

// Problem constants
#define BB   512
#define KK   512
#define DIN  1024
#define DOUT 4096
#define C3K  1536          // 3*K
#define NROWS (BB*KK)      // 262144
#define NIT   (C3K/32)     // 48 k32-iterations

#define EMB_BLOCKS 1184
#define SPLIT_BLOCKS 512
#define NWARPS_EMB (EMB_BLOCKS * 8)    // 9472

// Scratch (static device globals — no allocation)
__device__ float g_stats[6];
__device__ float g_coef[6];            // scale[3], shift[3]
__device__ float g_rsum[3 * DOUT];     // per-channel rowsums of W
__device__ int   g_cnt;
__device__ __align__(16) __nv_bfloat16 g_Ah[BB * C3K];    // hi(raw y)
__device__ __align__(16) __nv_bfloat16 g_Al[BB * C3K];    // lo(raw y)
__device__ __align__(16) __nv_bfloat16 g_Bh[DOUT * C3K];  // hi(raw W)
__device__ __align__(16) __nv_bfloat16 g_Bl[DOUT * C3K];  // lo(raw W)

__device__ __forceinline__ void cpa16(uint32_t dst, const void* src) {
    asm volatile("cp.async.cg.shared.global [%0], [%1], 16;" :: "r"(dst), "l"(src));
}
#define CPA_COMMIT() asm volatile("cp.async.commit_group;" ::: "memory")
#define CPA_WAIT(n)  asm volatile("cp.async.wait_group %0;" :: "n"(n) : "memory")

// ---------------------------------------------------------------------------
// k_front (R15 measured-best): blocks [0,1184): embed via per-warp cp.async
// row ring; blocks [1184,1696): raw-W bf16 split + per-channel rowsums.
// ---------------------------------------------------------------------------
__global__ __launch_bounds__(256, 2) void k_front(const float* __restrict__ x,
                                                  const float* __restrict__ Wemb,
                                                  const float* __restrict__ bemb,
                                                  const float* __restrict__ W) {
    extern __shared__ __align__(16) float4 sx[];   // [8 warps][3 slots][256]
    const int tid = threadIdx.x;
    const int wid = tid >> 5, lane = tid & 31;

    if (blockIdx.x >= EMB_BLOCKS) {
        const int row = (blockIdx.x - EMB_BLOCKS) * 8 + wid;
        const float4* wr = (const float4*)(W + (size_t)row * C3K);
        float rsum[3] = {0.f, 0.f, 0.f};
#pragma unroll
        for (int p = 0; p < 12; p++) {
            const int i = p * 32 + lane;
            const int o = i >> 7;
            float4 v = wr[i];
            rsum[o] += v.x + v.y + v.z + v.w;
            float a[4] = {v.x, v.y, v.z, v.w};
            __nv_bfloat16 h[4], l[4];
#pragma unroll
            for (int j = 0; j < 4; j++) {
                h[j] = __float2bfloat16_rn(a[j]);
                l[j] = __float2bfloat16_rn(a[j] - __bfloat162float(h[j]));
            }
            const size_t e = (size_t)row * C3K + i * 4;
            *(__nv_bfloat162*)&g_Bh[e]     = __nv_bfloat162(h[0], h[1]);
            *(__nv_bfloat162*)&g_Bh[e + 2] = __nv_bfloat162(h[2], h[3]);
            *(__nv_bfloat162*)&g_Bl[e]     = __nv_bfloat162(l[0], l[1]);
            *(__nv_bfloat162*)&g_Bl[e + 2] = __nv_bfloat162(l[2], l[3]);
        }
#pragma unroll
        for (int off = 16; off; off >>= 1)
#pragma unroll
            for (int o = 0; o < 3; o++)
                rsum[o] += __shfl_xor_sync(0xffffffffu, rsum[o], off);
        if (lane == 0) {
#pragma unroll
            for (int o = 0; o < 3; o++) g_rsum[o * DOUT + row] = rsum[o];
        }
        return;
    }

    // ---- embed path ----
    if (blockIdx.x == 0 && tid < 6) g_stats[tid] = 0.0f;

    float4 w0[8], w1[8], w2[8];
    const float4* W4 = (const float4*)Wemb;
#pragma unroll
    for (int j = 0; j < 8; j++) {
        w0[j] = W4[      j * 32 + lane];
        w1[j] = W4[256 + j * 32 + lane];
        w2[j] = W4[512 + j * 32 + lane];
    }
    const float b0 = bemb[0], b1 = bemb[1], b2 = bemb[2];

    const int gw = blockIdx.x * 8 + wid;
    const int nr = (NROWS - 1 - gw) / NWARPS_EMB + 1;
    float4* ring = sx + (size_t)wid * 3 * 256;
    const uint32_t sb = (uint32_t)__cvta_generic_to_shared(ring);

    auto issue = [&](int i) {
        const char* src = (const char*)x
            + ((size_t)gw + (size_t)i * NWARPS_EMB) * 4096 + lane * 16;
        const uint32_t dst = sb + (uint32_t)(i % 3) * 4096 + lane * 16;
#pragma unroll
        for (int c = 0; c < 8; c++)
            cpa16(dst + c * 512, src + c * 512);
        CPA_COMMIT();
    };

    issue(0);
    if (nr > 1) issue(1);

    for (int i = 0; i < nr; i++) {
        if (i + 1 < nr) CPA_WAIT(1);
        else CPA_WAIT(0);
        if (i + 2 < nr) issue(i + 2);

        const float4* xs = ring + (i % 3) * 256;
        float a0 = 0.f, a1 = 0.f, a2 = 0.f;
#pragma unroll
        for (int j = 0; j < 8; j++) {
            float4 xv = xs[j * 32 + lane];
            a0 += xv.x * w0[j].x + xv.y * w0[j].y + xv.z * w0[j].z + xv.w * w0[j].w;
            a1 += xv.x * w1[j].x + xv.y * w1[j].y + xv.z * w1[j].z + xv.w * w1[j].w;
            a2 += xv.x * w2[j].x + xv.y * w2[j].y + xv.z * w2[j].z + xv.w * w2[j].w;
        }
#pragma unroll
        for (int off = 16; off; off >>= 1) {
            a0 += __shfl_xor_sync(0xffffffffu, a0, off);
            a1 += __shfl_xor_sync(0xffffffffu, a1, off);
            a2 += __shfl_xor_sync(0xffffffffu, a2, off);
        }
        if (lane == 0) {
            const int row = gw + i * NWARPS_EMB;
            const int b = row >> 9, k = row & 511;
            const size_t base = (size_t)b * C3K + k;
            const float yv[3] = {a0 + b0, a1 + b1, a2 + b2};
#pragma unroll
            for (int o = 0; o < 3; o++) {
                __nv_bfloat16 h = __float2bfloat16_rn(yv[o]);
                __nv_bfloat16 l = __float2bfloat16_rn(yv[o] - __bfloat162float(h));
                g_Ah[base + o * 512] = h;
                g_Al[base + o * 512] = l;
            }
        }
    }
}
#define FRONT_SMEM (8 * 3 * 4096)    // 98304

// ---------------------------------------------------------------------------
// k_stats: BN stats over y = Ah + Al; last block finalizes coefs.
// ---------------------------------------------------------------------------
__global__ __launch_bounds__(256) void k_stats(const float* __restrict__ gamma,
                                               const float* __restrict__ beta) {
    const int tid = threadIdx.x;
    const int lane = tid & 31;
    float s[3] = {0.f, 0.f, 0.f};
    float q[3] = {0.f, 0.f, 0.f};
    const int stride = gridDim.x * blockDim.x;
    const uint4* h4 = (const uint4*)g_Ah;
    const uint4* l4 = (const uint4*)g_Al;
    const int n8 = (BB * C3K) / 8;
    for (int i = blockIdx.x * blockDim.x + tid; i < n8; i += stride) {
        const int o = (i % 192) >> 6;
        uint4 hv = h4[i], lv = l4[i];
#pragma unroll
        for (int w = 0; w < 4; w++) {
            __nv_bfloat162 hp = *(__nv_bfloat162*)&((&hv.x)[w]);
            __nv_bfloat162 lp = *(__nv_bfloat162*)&((&lv.x)[w]);
            float y0 = __bfloat162float(hp.x) + __bfloat162float(lp.x);
            float y1 = __bfloat162float(hp.y) + __bfloat162float(lp.y);
            s[o] += y0 + y1;
            q[o] += y0 * y0 + y1 * y1;
        }
    }
#pragma unroll
    for (int off = 16; off; off >>= 1) {
#pragma unroll
        for (int o = 0; o < 3; o++) {
            s[o] += __shfl_xor_sync(0xffffffffu, s[o], off);
            q[o] += __shfl_xor_sync(0xffffffffu, q[o], off);
        }
    }
    __shared__ float rs[6];
    __shared__ int is_last;
    if (tid < 6) rs[tid] = 0.f;
    __syncthreads();
    if (lane == 0) {
#pragma unroll
        for (int o = 0; o < 3; o++) {
            atomicAdd(&rs[o], s[o]);
            atomicAdd(&rs[3 + o], q[o]);
        }
    }
    __syncthreads();
    if (tid < 6) atomicAdd(&g_stats[tid], rs[tid]);
    if (tid == 0) {
        __threadfence();
        int old = atomicAdd(&g_cnt, 1);
        is_last = (old == (int)gridDim.x - 1) ? 1 : 0;
    }
    __syncthreads();
    if (is_last && tid == 0) {
        __threadfence();
        const float n = (float)NROWS;
#pragma unroll
        for (int o = 0; o < 3; o++) {
            float sm = atomicAdd(&g_stats[o], 0.0f);
            float sq = atomicAdd(&g_stats[3 + o], 0.0f);
            float mean = sm / n;
            float var  = sq / n - mean * mean;
            float sc   = gamma[o] * rsqrtf(var + 1e-5f);
            g_coef[o]     = sc;
            g_coef[3 + o] = beta[o] - mean * sc;
        }
        g_cnt = 0;
    }
}

// ---------------------------------------------------------------------------
// k_mma: raw-y @ raw-W, per-channel rescale at k boundaries.
// CTA 64x128, grid (32,8), **3 CTAs/SM** via 3-stage mbarrier cp.async ring
// (73.8 KB/CTA) and per-j fragment liveness (reg cap 84).
// ---------------------------------------------------------------------------
#define LDSM_X4(r0, r1, r2, r3, a) \
    asm volatile("ldmatrix.sync.aligned.m8n8.x4.shared.b16 {%0,%1,%2,%3}, [%4];" \
                 : "=r"(r0), "=r"(r1), "=r"(r2), "=r"(r3) : "r"(a))

#define MMA_BF16(d, a, b0r, b1r) \
    asm volatile("mma.sync.aligned.m16n8k16.row.col.f32.bf16.bf16.f32 " \
                 "{%0,%1,%2,%3},{%4,%5,%6,%7},{%8,%9},{%0,%1,%2,%3};" \
                 : "+f"((d)[0]), "+f"((d)[1]), "+f"((d)[2]), "+f"((d)[3]) \
                 : "r"((a)[0]), "r"((a)[1]), "r"((a)[2]), "r"((a)[3]), \
                   "r"(b0r), "r"(b1r))

#define MBAR_INIT(a, cnt) \
    asm volatile("mbarrier.init.shared.b64 [%0], %1;" :: "r"(a), "r"(cnt) : "memory")
#define MBAR_ARRIVE(a) \
    asm volatile("mbarrier.arrive.shared.b64 _, [%0];" :: "r"(a) : "memory")
#define CPA_MBAR_ARRIVE(a) \
    asm volatile("cp.async.mbarrier.arrive.noinc.shared.b64 [%0];" :: "r"(a) : "memory")
#define MBAR_WAIT(a, ph) do {                                                  \
    uint32_t _d;                                                               \
    asm volatile("{\n\t.reg .pred p;\n\t"                                      \
        "mbarrier.try_wait.parity.acquire.cta.shared::cta.b64 p, [%1], %2;\n\t"\
        "selp.b32 %0,1,0,p;\n\t}" : "=r"(_d) : "r"(a), "r"((uint32_t)(ph)) : "memory"); \
    if (!_d) {                                                                 \
        asm volatile("{\n\t.reg .pred P1;\n"                                   \
            "WL_%=:\n\t"                                                       \
            "mbarrier.try_wait.parity.acquire.cta.shared::cta.b64 P1, [%0], %1, 0x989680;\n\t" \
            "@P1 bra.uni WD_%=;\n\t"                                           \
            "bra.uni WL_%=;\n"                                                 \
            "WD_%=:\n\t}" :: "r"(a), "r"((uint32_t)(ph)) : "memory");          \
    } } while (0)

__device__ __forceinline__ uint32_t tswz(int row, int c) {
    return (uint32_t)(row * 64 + ((c ^ ((row ^ (row >> 2)) & 3)) << 4));
}

#define TILE_A   4096
#define TILE_BB  8192
#define STAGE_B  (2 * TILE_A + 2 * TILE_BB)   // 24576
#define RING_B   (3 * STAGE_B)                // 73728 (3-stage ring)
#define SMEM_B   (RING_B + 64)                // 73792 -> 3 CTAs/SM

__global__ __launch_bounds__(256, 3) void k_mma(float* __restrict__ out) {
    extern __shared__ __align__(128) char smem[];
    const uint32_t sbase = (uint32_t)__cvta_generic_to_shared(smem);
    const uint32_t fbar0 = sbase + RING_B;
    const uint32_t ebar0 = sbase + RING_B + 32;

    const int tid = threadIdx.x;
    const int wid = tid >> 5, lane = tid & 31;
    const int warp_m = wid & 1;
    const int warp_n = wid >> 1;
    const int bn = blockIdx.x;
    const int bm = blockIdx.y;

    if (tid == 0) {
#pragma unroll
        for (int s = 0; s < 3; s++) {
            MBAR_INIT(fbar0 + s * 8, 256);
            MBAR_INIT(ebar0 + s * 8, 8);
        }
    }
    __syncthreads();

    const float sc0 = g_coef[0], sc1 = g_coef[1], sc2 = g_coef[2];
    const float sh0 = g_coef[3], sh1 = g_coef[4], sh2 = g_coef[5];
    const float r01 = sc0 / sc1, r12 = sc1 / sc2;

    const int srow = tid >> 2, scn = tid & 3;
    const __nv_bfloat16* gA[2] = {
        g_Ah + (size_t)(bm * 64 + srow) * C3K + scn * 8,
        g_Al + (size_t)(bm * 64 + srow) * C3K + scn * 8};
    const __nv_bfloat16* gB[2] = {
        g_Bh + (size_t)(bn * 128 + srow) * C3K + scn * 8,
        g_Bl + (size_t)(bn * 128 + srow) * C3K + scn * 8};
    const uint32_t soffA  = tswz(srow, scn);
    const uint32_t soffB0 = tswz(srow, scn);
    const uint32_t soffB1 = tswz(srow + 64, scn);
    const size_t bstride64 = (size_t)64 * C3K;

    uint32_t offA[2][2], offB[2][2];
#pragma unroll
    for (int mf = 0; mf < 2; mf++)
#pragma unroll
        for (int j = 0; j < 2; j++)
            offA[mf][j] = tswz(warp_m * 32 + mf * 16 + (lane & 15),
                               2 * j + (lane >> 4));
#pragma unroll
    for (int ng = 0; ng < 2; ng++)
#pragma unroll
        for (int j = 0; j < 2; j++)
            offB[ng][j] = tswz(warp_n * 32 + ng * 16 + ((lane >> 4) << 3) + (lane & 7),
                               2 * j + ((lane >> 3) & 1));

    float acc[2][4][4];
#pragma unroll
    for (int mf = 0; mf < 2; mf++)
#pragma unroll
        for (int nf = 0; nf < 4; nf++)
#pragma unroll
            for (int r = 0; r < 4; r++) acc[mf][nf][r] = 0.f;

    // Producer cursor (mod-3 ring)
    int ps = 0;
    uint32_t pph = 1;   // first empty-wait passes immediately
    auto produce = [&](int it2) {
        MBAR_WAIT(ebar0 + ps * 8, pph);
        const uint32_t st = sbase + ps * STAGE_B;
        const int koff = it2 * 32;
        cpa16(st + 0 * TILE_A + soffA, gA[0] + koff);
        cpa16(st + 1 * TILE_A + soffA, gA[1] + koff);
        const uint32_t bbase = st + 2 * TILE_A;
        cpa16(bbase + soffB0,           gB[0] + koff);
        cpa16(bbase + soffB1,           gB[0] + koff + bstride64);
        cpa16(bbase + TILE_BB + soffB0, gB[1] + koff);
        cpa16(bbase + TILE_BB + soffB1, gB[1] + koff + bstride64);
        CPA_MBAR_ARRIVE(fbar0 + ps * 8);
        if (++ps == 3) { ps = 0; pph ^= 1; }
    };

    produce(0); produce(1);

    // Consumer cursor
    int cs = 0;
    uint32_t cph = 0;

    for (int it = 0; it < NIT; it++) {
        MBAR_WAIT(fbar0 + cs * 8, cph);
        if (it + 2 < NIT) produce(it + 2);

        const uint32_t stg = sbase + cs * STAGE_B;
        const uint32_t bstg = stg + 2 * TILE_A;

#pragma unroll
        for (int j = 0; j < 2; j++) {
            // per-j fragment loads (halved liveness vs holding both j-steps)
            uint32_t ah[2][4], al[2][4], bh[2][4], bl[2][4];
#pragma unroll
            for (int mf = 0; mf < 2; mf++) {
                LDSM_X4(ah[mf][0], ah[mf][1], ah[mf][2], ah[mf][3],
                        stg + 0 * TILE_A + offA[mf][j]);
                LDSM_X4(al[mf][0], al[mf][1], al[mf][2], al[mf][3],
                        stg + 1 * TILE_A + offA[mf][j]);
            }
#pragma unroll
            for (int ng = 0; ng < 2; ng++) {
                LDSM_X4(bh[ng][0], bh[ng][1], bh[ng][2], bh[ng][3],
                        bstg + offB[ng][j]);
                LDSM_X4(bl[ng][0], bl[ng][1], bl[ng][2], bl[ng][3],
                        bstg + TILE_BB + offB[ng][j]);
            }
            if (j == 1 && lane == 0) MBAR_ARRIVE(ebar0 + cs * 8);

#pragma unroll
            for (int mf = 0; mf < 2; mf++) {
#pragma unroll
                for (int nf = 0; nf < 4; nf++) {
                    const int ng = nf >> 1, hb = (nf & 1) * 2;
                    MMA_BF16(acc[mf][nf], ah[mf], bh[ng][hb], bh[ng][hb + 1]);
                    MMA_BF16(acc[mf][nf], ah[mf], bl[ng][hb], bl[ng][hb + 1]);
                    MMA_BF16(acc[mf][nf], al[mf], bh[ng][hb], bh[ng][hb + 1]);
                }
            }
        }

        if (it == 15 || it == 31) {
            const float r = (it == 15) ? r01 : r12;
#pragma unroll
            for (int mf = 0; mf < 2; mf++)
#pragma unroll
                for (int nf = 0; nf < 4; nf++)
#pragma unroll
                    for (int q = 0; q < 4; q++) acc[mf][nf][q] *= r;
        }

        if (++cs == 3) { cs = 0; cph ^= 1; }
    }

    const int mbase = bm * 64 + warp_m * 32 + (lane >> 2);
    const int nbase = bn * 128 + warp_n * 32 + 2 * (lane & 3);
#pragma unroll
    for (int mf = 0; mf < 2; mf++) {
#pragma unroll
        for (int nf = 0; nf < 4; nf++) {
            const int m = mbase + mf * 16;
            const int n = nbase + nf * 8;
            const float bz0 = sh0 * g_rsum[n] + sh1 * g_rsum[DOUT + n]
                            + sh2 * g_rsum[2 * DOUT + n];
            const float bz1 = sh0 * g_rsum[n + 1] + sh1 * g_rsum[DOUT + n + 1]
                            + sh2 * g_rsum[2 * DOUT + n + 1];
            *(float2*)(out + (size_t)m * DOUT + n) =
                make_float2(acc[mf][nf][0] * sc2 + bz0, acc[mf][nf][1] * sc2 + bz1);
            *(float2*)(out + (size_t)(m + 8) * DOUT + n) =
                make_float2(acc[mf][nf][2] * sc2 + bz0, acc[mf][nf][3] * sc2 + bz1);
        }
    }
}

// ---------------------------------------------------------------------------
// Launch
// ---------------------------------------------------------------------------
extern "C" void kernel_launch(void* const* d_in, const int* in_sizes, int n_in,
                              void* d_out, int out_size) {
    const float* x     = (const float*)d_in[0];
    const float* Wemb  = (const float*)d_in[1];
    const float* bemb  = (const float*)d_in[2];
    const float* gamma = (const float*)d_in[3];
    const float* beta  = (const float*)d_in[4];
    const float* Wfc2  = (const float*)d_in[5];
    float* out = (float*)d_out;

    static int smem_set = 0;
    if (!smem_set) {
        cudaFuncSetAttribute(k_mma, cudaFuncAttributeMaxDynamicSharedMemorySize, SMEM_B);
        cudaFuncSetAttribute(k_front, cudaFuncAttributeMaxDynamicSharedMemorySize, FRONT_SMEM);
        smem_set = 1;
    }

    k_front<<<EMB_BLOCKS + SPLIT_BLOCKS, 256, FRONT_SMEM>>>(x, Wemb, bemb, Wfc2);
    k_stats<<<148, 256>>>(gamma, beta);
    k_mma<<<dim3(32, 8), 256, SMEM_B>>>(out);
}